// round 1
// baseline (speedup 1.0000x reference)
#include <cuda_runtime.h>

#define B_  256
#define T_  2048
#define H_  64
#define O_  2
#define NROWS (B_ * T_)

// Scratch (device globals — no allocation allowed in kernel_launch)
__device__ float g_bufA[NROWS * H_];
__device__ float g_bufB[NROWS * H_];

// ---------- packed f32x2 helpers (sm_103a FFMA2 path) ----------
static __device__ __forceinline__ unsigned long long pack2(float lo, float hi) {
    unsigned long long r;
    asm("mov.b64 %0, {%1, %2};" : "=l"(r) : "f"(lo), "f"(hi));
    return r;
}
static __device__ __forceinline__ void unpack2(unsigned long long v, float& a, float& b) {
    asm("mov.b64 {%0, %1}, %2;" : "=f"(a), "=f"(b) : "l"(v));
}
static __device__ __forceinline__ unsigned long long fma2(unsigned long long a,
                                                          unsigned long long b,
                                                          unsigned long long c) {
    unsigned long long d;
    asm("fma.rn.f32x2 %0, %1, %2, %3;" : "=l"(d) : "l"(a), "l"(b), "l"(c));
    return d;
}
static __device__ __forceinline__ unsigned long long add2(unsigned long long a,
                                                          unsigned long long b) {
    unsigned long long d;
    asm("add.rn.f32x2 %0, %1, %2;" : "=l"(d) : "l"(a), "l"(b));
    return d;
}

// Accurate-enough fast tanh: rel err ~1e-7 via MUFU.EX2 + MUFU.RCP.
// Saturates correctly at +-1 for large |x|.
static __device__ __forceinline__ float fast_tanh(float x) {
    float e = __expf(2.0f * x);
    return 1.0f - __fdividef(2.0f, e + 1.0f);
}

// ============================================================================
// gemm64: out[r][j] = sum_k in[r][k] * W[j][k] + ba[j] + bb[j]
// One warp per row (grid-stride). Lane l owns outputs j=l and j=l+32,
// with W rows (l, l+32) packed into 64 b64 registers (amortized across rows).
// x row is staged into smem as duplicated (v,v) pairs -> inner loop is
// 32x LDS.128 + 64x fma.rn.f32x2.
// ============================================================================
__global__ void __launch_bounds__(128) gemm64_kernel(
    const float* __restrict__ in, const float* __restrict__ W,
    const float* __restrict__ ba, const float* __restrict__ bb,
    float* __restrict__ out, int nrows)
{
    __shared__ __align__(16) unsigned long long xd[4][2][64];
    const int l   = threadIdx.x & 31;
    const int wrp = threadIdx.x >> 5;

    unsigned long long w[64];
#pragma unroll
    for (int k = 0; k < 64; k++)
        w[k] = pack2(W[l * 64 + k], W[(l + 32) * 64 + k]);

    const unsigned long long binit =
        pack2(ba[l] + bb[l], ba[l + 32] + bb[l + 32]);

    const int warpId = blockIdx.x * 4 + wrp;
    const int nw     = gridDim.x * 4;

    long r = warpId;
    if (r >= nrows) return;
    float x0 = in[r * 64 + l];
    float x1 = in[r * 64 + 32 + l];
    int buf = 0;

    while (r < nrows) {
        xd[wrp][buf][l]      = pack2(x0, x0);
        xd[wrp][buf][l + 32] = pack2(x1, x1);
        __syncwarp();

        long rn = r + nw;
        if (rn < nrows) {            // prefetch next row while FMAs run
            x0 = in[rn * 64 + l];
            x1 = in[rn * 64 + 32 + l];
        }

        unsigned long long a0 = binit, a1 = 0ull, a2 = 0ull, a3 = 0ull;
#pragma unroll
        for (int k = 0; k < 64; k += 4) {
            const ulonglong2* hp =
                reinterpret_cast<const ulonglong2*>(&xd[wrp][buf][k]);
            ulonglong2 v0 = hp[0];
            ulonglong2 v1 = hp[1];
            a0 = fma2(w[k + 0], v0.x, a0);
            a1 = fma2(w[k + 1], v0.y, a1);
            a2 = fma2(w[k + 2], v1.x, a2);
            a3 = fma2(w[k + 3], v1.y, a3);
        }
        unsigned long long s = add2(add2(a0, a1), add2(a2, a3));
        float o0, o1;
        unpack2(s, o0, o1);
        out[r * 64 + l]      = o0;
        out[r * 64 + 32 + l] = o1;

        buf ^= 1;
        r = rn;
    }
}

// ============================================================================
// scan: h_t = tanh(xin_t + W_hh h_{t-1}), one warp per batch element.
// h kept in smem as duplicated (v,v) b64 pairs, double-buffered ->
// exactly one __syncwarp() per timestep. W_hh packed in 64 b64 regs.
// ============================================================================
__global__ void __launch_bounds__(32) scan_kernel(
    const float* __restrict__ xin, const float* __restrict__ Whh,
    float* __restrict__ hout)
{
    __shared__ __align__(16) unsigned long long hd[2][64];
    const int l = threadIdx.x;
    const int b = blockIdx.x;

    unsigned long long w[64];
#pragma unroll
    for (int k = 0; k < 64; k++)
        w[k] = pack2(Whh[l * 64 + k], Whh[(l + 32) * 64 + k]);

    hd[0][l]      = 0ull;
    hd[0][l + 32] = 0ull;
    __syncwarp();

    const float* xb = xin + (long)b * T_ * 64;
    float*       hb = hout + (long)b * T_ * 64;

    float x0 = xb[l];
    float x1 = xb[32 + l];
    int p = 0;

    for (int t = 0; t < T_; t++) {
        float nx0 = 0.f, nx1 = 0.f;
        if (t + 1 < T_) {            // prefetch next timestep's xin
            nx0 = xb[(t + 1) * 64 + l];
            nx1 = xb[(t + 1) * 64 + 32 + l];
        }

        unsigned long long a0 = pack2(x0, x1), a1 = 0ull, a2 = 0ull, a3 = 0ull;
#pragma unroll
        for (int k = 0; k < 64; k += 4) {
            const ulonglong2* hp =
                reinterpret_cast<const ulonglong2*>(&hd[p][k]);
            ulonglong2 v0 = hp[0];
            ulonglong2 v1 = hp[1];
            a0 = fma2(w[k + 0], v0.x, a0);
            a1 = fma2(w[k + 1], v0.y, a1);
            a2 = fma2(w[k + 2], v1.x, a2);
            a3 = fma2(w[k + 3], v1.y, a3);
        }
        unsigned long long s = add2(add2(a0, a1), add2(a2, a3));
        float s0, s1;
        unpack2(s, s0, s1);
        float h0v = fast_tanh(s0);
        float h1v = fast_tanh(s1);

        hb[t * 64 + l]      = h0v;
        hb[t * 64 + 32 + l] = h1v;
        hd[p ^ 1][l]      = pack2(h0v, h0v);
        hd[p ^ 1][l + 32] = pack2(h1v, h1v);
        __syncwarp();

        p ^= 1;
        x0 = nx0;
        x1 = nx1;
    }
}

// ============================================================================
// head: z = relu(h W1^T + b1); out = z W2^T + b2  (O=2)
// Same warp-per-row structure; W2 contribution via warp shuffle reduction.
// ============================================================================
__global__ void __launch_bounds__(128) head_kernel(
    const float* __restrict__ hin, const float* __restrict__ W1,
    const float* __restrict__ b1, const float* __restrict__ W2,
    const float* __restrict__ b2, float* __restrict__ out, int nrows)
{
    __shared__ __align__(16) unsigned long long xd[4][2][64];
    const int l   = threadIdx.x & 31;
    const int wrp = threadIdx.x >> 5;

    unsigned long long w[64];
#pragma unroll
    for (int k = 0; k < 64; k++)
        w[k] = pack2(W1[l * 64 + k], W1[(l + 32) * 64 + k]);
    const unsigned long long binit = pack2(b1[l], b1[l + 32]);

    const float w20l = W2[l],      w20h = W2[32 + l];
    const float w21l = W2[64 + l], w21h = W2[96 + l];
    const float b20 = b2[0], b21 = b2[1];

    const int warpId = blockIdx.x * 4 + wrp;
    const int nw     = gridDim.x * 4;

    long r = warpId;
    if (r >= nrows) return;
    float x0 = hin[r * 64 + l];
    float x1 = hin[r * 64 + 32 + l];
    int buf = 0;

    while (r < nrows) {
        xd[wrp][buf][l]      = pack2(x0, x0);
        xd[wrp][buf][l + 32] = pack2(x1, x1);
        __syncwarp();

        long rn = r + nw;
        if (rn < nrows) {
            x0 = hin[rn * 64 + l];
            x1 = hin[rn * 64 + 32 + l];
        }

        unsigned long long a0 = binit, a1 = 0ull, a2 = 0ull, a3 = 0ull;
#pragma unroll
        for (int k = 0; k < 64; k += 4) {
            const ulonglong2* hp =
                reinterpret_cast<const ulonglong2*>(&xd[wrp][buf][k]);
            ulonglong2 v0 = hp[0];
            ulonglong2 v1 = hp[1];
            a0 = fma2(w[k + 0], v0.x, a0);
            a1 = fma2(w[k + 1], v0.y, a1);
            a2 = fma2(w[k + 2], v1.x, a2);
            a3 = fma2(w[k + 3], v1.y, a3);
        }
        unsigned long long s = add2(add2(a0, a1), add2(a2, a3));
        float z0, z1;
        unpack2(s, z0, z1);
        z0 = fmaxf(z0, 0.f);
        z1 = fmaxf(z1, 0.f);

        float p0 = z0 * w20l + z1 * w20h;
        float p1 = z0 * w21l + z1 * w21h;
#pragma unroll
        for (int off = 16; off; off >>= 1) {
            p0 += __shfl_xor_sync(0xffffffffu, p0, off);
            p1 += __shfl_xor_sync(0xffffffffu, p1, off);
        }
        if (l == 0)
            *reinterpret_cast<float2*>(&out[r * 2]) =
                make_float2(p0 + b20, p1 + b21);

        buf ^= 1;
        r = rn;
    }
}

// ============================================================================
extern "C" void kernel_launch(void* const* d_in, const int* in_sizes, int n_in,
                              void* d_out, int out_size)
{
    const float* x     = (const float*)d_in[0];
    const float* W_ih0 = (const float*)d_in[1];
    const float* W_hh0 = (const float*)d_in[2];
    const float* b_ih0 = (const float*)d_in[3];
    const float* b_hh0 = (const float*)d_in[4];
    const float* W_ih1 = (const float*)d_in[5];
    const float* W_hh1 = (const float*)d_in[6];
    const float* b_ih1 = (const float*)d_in[7];
    const float* b_hh1 = (const float*)d_in[8];
    const float* W1    = (const float*)d_in[9];
    const float* b1    = (const float*)d_in[10];
    const float* W2    = (const float*)d_in[11];
    const float* b2    = (const float*)d_in[12];
    float* out = (float*)d_out;

    static float* bufA = nullptr;
    static float* bufB = nullptr;
    if (!bufA) {  // resolved on the (uncaptured) correctness call; pure query, no alloc
        cudaGetSymbolAddress((void**)&bufA, g_bufA);
        cudaGetSymbolAddress((void**)&bufB, g_bufB);
    }

    const int GRID = 1184;  // 8 blocks/SM worth of warps for grid-stride GEMMs

    // xin0 = x W_ih0^T + b_ih0 + b_hh0
    gemm64_kernel<<<GRID, 128>>>(x, W_ih0, b_ih0, b_hh0, bufA, NROWS);
    // layer-0 recurrence -> h0
    scan_kernel<<<B_, 32>>>(bufA, W_hh0, bufB);
    // xin1 = h0 W_ih1^T + b_ih1 + b_hh1
    gemm64_kernel<<<GRID, 128>>>(bufB, W_ih1, b_ih1, b_hh1, bufA, NROWS);
    // layer-1 recurrence -> h1
    scan_kernel<<<B_, 32>>>(bufA, W_hh1, bufB);
    // head
    head_kernel<<<GRID, 128>>>(bufB, W1, b1, W2, b2, out, NROWS);
}

// round 2
// speedup vs baseline: 1.6935x; 1.6935x over previous
#include <cuda_runtime.h>

#define B_  256
#define T_  2048
#define H_  64
#define O_  2
#define NROWS (B_ * T_)
#define PF  8   // scan xin prefetch depth (T_ % PF == 0)

// Scratch (device globals — no allocation allowed in kernel_launch)
__device__ float g_bufA[NROWS * H_];
__device__ float g_bufB[NROWS * H_];

// ---------- packed f32x2 helpers (sm_103a FFMA2 path) ----------
static __device__ __forceinline__ unsigned long long pack2(float lo, float hi) {
    unsigned long long r;
    asm("mov.b64 %0, {%1, %2};" : "=l"(r) : "f"(lo), "f"(hi));
    return r;
}
static __device__ __forceinline__ void unpack2(unsigned long long v, float& a, float& b) {
    asm("mov.b64 {%0, %1}, %2;" : "=f"(a), "=f"(b) : "l"(v));
}
static __device__ __forceinline__ unsigned long long fma2(unsigned long long a,
                                                          unsigned long long b,
                                                          unsigned long long c) {
    unsigned long long d;
    asm("fma.rn.f32x2 %0, %1, %2, %3;" : "=l"(d) : "l"(a), "l"(b), "l"(c));
    return d;
}
static __device__ __forceinline__ unsigned long long add2(unsigned long long a,
                                                          unsigned long long b) {
    unsigned long long d;
    asm("add.rn.f32x2 %0, %1, %2;" : "=l"(d) : "l"(a), "l"(b));
    return d;
}

// Fast tanh, rel err ~1e-7, saturates correctly.
static __device__ __forceinline__ float fast_tanh(float x) {
    float e = __expf(2.0f * x);
    return 1.0f - __fdividef(2.0f, e + 1.0f);
}

// ============================================================================
// gemm64: out[r][j] = sum_k in[r][k] * W[j][k] + ba[j] + bb[j]
// Warp per row (grid-stride). K-paired f32x2: acc halves hold (even-k, odd-k)
// partials of ONE output, x row staged in smem in natural pair layout so all
// LDS.128 are warp-uniform broadcasts (1 crossbar phase). Weights load as u64.
// ============================================================================
__global__ void __launch_bounds__(128) gemm64_kernel(
    const float* __restrict__ in, const float* __restrict__ W,
    const float* __restrict__ ba, const float* __restrict__ bb,
    float* __restrict__ out, int nrows)
{
    __shared__ __align__(16) unsigned long long xsm[4][2][32];
    const int l   = threadIdx.x & 31;
    const int wrp = threadIdx.x >> 5;
    const unsigned long long* Wu = (const unsigned long long*)W;
    const unsigned long long* Iu = (const unsigned long long*)in;

    unsigned long long wl[32], wh[32];
#pragma unroll
    for (int k = 0; k < 32; k++) {
        wl[k] = Wu[l * 32 + k];          // (W[l][2k],   W[l][2k+1])
        wh[k] = Wu[(l + 32) * 32 + k];   // (W[l+32][2k],W[l+32][2k+1])
    }
    const float biasl = ba[l] + bb[l];
    const float biash = ba[l + 32] + bb[l + 32];

    const int warpId = blockIdx.x * 4 + wrp;
    const int nw     = gridDim.x * 4;

    long r = warpId;
    if (r >= nrows) return;
    unsigned long long xv = Iu[r * 32 + l];   // (x[2l], x[2l+1])
    int buf = 0;

    while (r < nrows) {
        xsm[wrp][buf][l] = xv;
        __syncwarp();

        long rn = r + nw;
        if (rn < nrows) xv = Iu[rn * 32 + l];   // prefetch next row

        unsigned long long a0 = pack2(biasl, 0.f), a1 = 0ull;
        unsigned long long c0 = pack2(biash, 0.f), c1 = 0ull;
        const ulonglong2* xp = (const ulonglong2*)&xsm[wrp][buf][0];
#pragma unroll
        for (int k = 0; k < 32; k += 2) {
            ulonglong2 v = xp[k >> 1];           // broadcast LDS.128
            a0 = fma2(wl[k],     v.x, a0);
            a1 = fma2(wl[k + 1], v.y, a1);
            c0 = fma2(wh[k],     v.x, c0);
            c1 = fma2(wh[k + 1], v.y, c1);
        }
        float s0, s1, t0, t1;
        unpack2(add2(a0, a1), s0, s1);
        unpack2(add2(c0, c1), t0, t1);
        out[r * 64 + l]      = s0 + s1;
        out[r * 64 + 32 + l] = t0 + t1;

        buf ^= 1;
        r = rn;
    }
}

// ============================================================================
// scan: h_t = tanh(xin_t + W_hh h_{t-1}).
// 128-thread block = 2 batches x 2 warps. Warp (bl,half) computes outputs
// j = half*32 + lane. h exchanged via smem floats (natural pair layout ->
// broadcast LDS.128 reads). 8-deep register prefetch of xin covers DRAM.
// One __syncthreads per step.
// ============================================================================
__global__ void __launch_bounds__(128) scan_kernel(
    const float* __restrict__ xin, const float* __restrict__ Whh,
    float* __restrict__ hout)
{
    __shared__ __align__(16) float hsm[2][2][64];
    const int l    = threadIdx.x & 31;
    const int wid  = threadIdx.x >> 5;
    const int bl   = wid >> 1;        // batch within block
    const int half = wid & 1;         // output half
    const int j    = half * 32 + l;   // owned output index
    const int b    = blockIdx.x * 2 + bl;

    const unsigned long long* Wu = (const unsigned long long*)Whh;
    unsigned long long w[32];
#pragma unroll
    for (int k = 0; k < 32; k++) w[k] = Wu[j * 32 + k];  // (W[j][2k], W[j][2k+1])

    hsm[bl][0][j] = 0.f;

    const float* xb = xin  + (long)b * T_ * 64;
    float*       hb = hout + (long)b * T_ * 64;

    float xs[PF];
#pragma unroll
    for (int s = 0; s < PF; s++) xs[s] = xb[s * 64 + j];

    __syncthreads();

    int p = 0;
    for (int tb = 0; tb < T_; tb += PF) {
#pragma unroll
        for (int u = 0; u < PF; u++) {
            const int t = tb + u;
            const float xv = xs[u];
            if (t + PF < T_) xs[u] = xb[(t + PF) * 64 + j];  // deep prefetch

            unsigned long long a0 = pack2(xv, 0.f), a1 = 0ull, a2 = 0ull, a3 = 0ull;
            const ulonglong2* hp = (const ulonglong2*)&hsm[bl][p][0];
#pragma unroll
            for (int k = 0; k < 32; k += 4) {
                ulonglong2 v0 = hp[(k >> 1)];        // broadcast LDS.128
                ulonglong2 v1 = hp[(k >> 1) + 1];
                a0 = fma2(w[k],     v0.x, a0);
                a1 = fma2(w[k + 1], v0.y, a1);
                a2 = fma2(w[k + 2], v1.x, a2);
                a3 = fma2(w[k + 3], v1.y, a3);
            }
            float s0, s1;
            unpack2(add2(add2(a0, a1), add2(a2, a3)), s0, s1);
            const float hv = fast_tanh(s0 + s1);

            hb[t * 64 + j]     = hv;
            hsm[bl][p ^ 1][j]  = hv;
            __syncthreads();
            p ^= 1;
        }
    }
}

// ============================================================================
// head: z = relu(h W1^T + b1); out = z W2^T + b2  (O=2)
// ============================================================================
__global__ void __launch_bounds__(128) head_kernel(
    const float* __restrict__ hin, const float* __restrict__ W1,
    const float* __restrict__ b1, const float* __restrict__ W2,
    const float* __restrict__ b2, float* __restrict__ out, int nrows)
{
    __shared__ __align__(16) unsigned long long xsm[4][2][32];
    const int l   = threadIdx.x & 31;
    const int wrp = threadIdx.x >> 5;
    const unsigned long long* Wu = (const unsigned long long*)W1;
    const unsigned long long* Iu = (const unsigned long long*)hin;

    unsigned long long wl[32], wh[32];
#pragma unroll
    for (int k = 0; k < 32; k++) {
        wl[k] = Wu[l * 32 + k];
        wh[k] = Wu[(l + 32) * 32 + k];
    }
    const float biasl = b1[l], biash = b1[l + 32];
    const float w20l = W2[l],      w20h = W2[32 + l];
    const float w21l = W2[64 + l], w21h = W2[96 + l];
    const float b20 = b2[0], b21 = b2[1];

    const int warpId = blockIdx.x * 4 + wrp;
    const int nw     = gridDim.x * 4;

    long r = warpId;
    if (r >= nrows) return;
    unsigned long long xv = Iu[r * 32 + l];
    int buf = 0;

    while (r < nrows) {
        xsm[wrp][buf][l] = xv;
        __syncwarp();

        long rn = r + nw;
        if (rn < nrows) xv = Iu[rn * 32 + l];

        unsigned long long a0 = pack2(biasl, 0.f), a1 = 0ull;
        unsigned long long c0 = pack2(biash, 0.f), c1 = 0ull;
        const ulonglong2* xp = (const ulonglong2*)&xsm[wrp][buf][0];
#pragma unroll
        for (int k = 0; k < 32; k += 2) {
            ulonglong2 v = xp[k >> 1];
            a0 = fma2(wl[k],     v.x, a0);
            a1 = fma2(wl[k + 1], v.y, a1);
            c0 = fma2(wh[k],     v.x, c0);
            c1 = fma2(wh[k + 1], v.y, c1);
        }
        float s0, s1, t0, t1;
        unpack2(add2(a0, a1), s0, s1);
        unpack2(add2(c0, c1), t0, t1);
        float z0 = fmaxf(s0 + s1, 0.f);
        float z1 = fmaxf(t0 + t1, 0.f);

        float p0 = z0 * w20l + z1 * w20h;
        float p1 = z0 * w21l + z1 * w21h;
#pragma unroll
        for (int off = 16; off; off >>= 1) {
            p0 += __shfl_xor_sync(0xffffffffu, p0, off);
            p1 += __shfl_xor_sync(0xffffffffu, p1, off);
        }
        if (l == 0)
            *reinterpret_cast<float2*>(&out[r * 2]) =
                make_float2(p0 + b20, p1 + b21);

        buf ^= 1;
        r = rn;
    }
}

// ============================================================================
extern "C" void kernel_launch(void* const* d_in, const int* in_sizes, int n_in,
                              void* d_out, int out_size)
{
    const float* x     = (const float*)d_in[0];
    const float* W_ih0 = (const float*)d_in[1];
    const float* W_hh0 = (const float*)d_in[2];
    const float* b_ih0 = (const float*)d_in[3];
    const float* b_hh0 = (const float*)d_in[4];
    const float* W_ih1 = (const float*)d_in[5];
    const float* W_hh1 = (const float*)d_in[6];
    const float* b_ih1 = (const float*)d_in[7];
    const float* b_hh1 = (const float*)d_in[8];
    const float* W1    = (const float*)d_in[9];
    const float* b1    = (const float*)d_in[10];
    const float* W2    = (const float*)d_in[11];
    const float* b2    = (const float*)d_in[12];
    float* out = (float*)d_out;

    static float* bufA = nullptr;
    static float* bufB = nullptr;
    if (!bufA) {
        cudaGetSymbolAddress((void**)&bufA, g_bufA);
        cudaGetSymbolAddress((void**)&bufB, g_bufB);
    }

    const int GRID = 1184;  // 32 warps/SM for the data-parallel kernels

    gemm64_kernel<<<GRID, 128>>>(x, W_ih0, b_ih0, b_hh0, bufA, NROWS);
    scan_kernel<<<B_ / 2, 128>>>(bufA, W_hh0, bufB);
    gemm64_kernel<<<GRID, 128>>>(bufB, W_ih1, b_ih1, b_hh1, bufA, NROWS);
    scan_kernel<<<B_ / 2, 128>>>(bufA, W_hh1, bufB);
    head_kernel<<<GRID, 128>>>(bufB, W1, b1, W2, b2, out, NROWS);
}

// round 3
// speedup vs baseline: 1.7867x; 1.0550x over previous
#include <cuda_runtime.h>

#define B_  256
#define T_  2048
#define H_  64
#define O_  2
#define NROWS (B_ * T_)
#define PF  8   // scan xin prefetch depth (T_ % PF == 0)

// Scratch (device globals — no allocation allowed in kernel_launch)
__device__ float g_bufA[NROWS * H_];
__device__ float g_bufB[NROWS * H_];

// ---------- packed f32x2 helpers (sm_103a FFMA2 path) ----------
static __device__ __forceinline__ unsigned long long pack2(float lo, float hi) {
    unsigned long long r;
    asm("mov.b64 %0, {%1, %2};" : "=l"(r) : "f"(lo), "f"(hi));
    return r;
}
static __device__ __forceinline__ void unpack2(unsigned long long v, float& a, float& b) {
    asm("mov.b64 {%0, %1}, %2;" : "=f"(a), "=f"(b) : "l"(v));
}
static __device__ __forceinline__ unsigned long long fma2(unsigned long long a,
                                                          unsigned long long b,
                                                          unsigned long long c) {
    unsigned long long d;
    asm("fma.rn.f32x2 %0, %1, %2, %3;" : "=l"(d) : "l"(a), "l"(b), "l"(c));
    return d;
}
static __device__ __forceinline__ unsigned long long add2(unsigned long long a,
                                                          unsigned long long b) {
    unsigned long long d;
    asm("add.rn.f32x2 %0, %1, %2;" : "=l"(d) : "l"(a), "l"(b));
    return d;
}

// Fast tanh, rel err ~1e-7, saturates correctly.
static __device__ __forceinline__ float fast_tanh(float x) {
    float e = __expf(2.0f * x);
    return 1.0f - __fdividef(2.0f, e + 1.0f);
}

#define NAMED_BAR(id, cnt) asm volatile("bar.sync %0, %1;" :: "r"(id), "r"(cnt) : "memory")

// ============================================================================
// gemm64: out[r][j] = sum_k in[r][k] * W[j][k] + ba[j] + bb[j]
// Warp handles 2 rows per iteration (independent acc chains -> ILP, MLP=2,
// one __syncwarp per 2 rows). K-paired f32x2 accumulation, x rows staged in
// smem natural pair layout -> broadcast LDS.128.
// ============================================================================
__global__ void __launch_bounds__(128) gemm64_kernel(
    const float* __restrict__ in, const float* __restrict__ W,
    const float* __restrict__ ba, const float* __restrict__ bb,
    float* __restrict__ out, int nrows)
{
    __shared__ __align__(16) unsigned long long xsm[4][2][2][32]; // [warp][buf][row01][pair]
    const int l   = threadIdx.x & 31;
    const int wrp = threadIdx.x >> 5;
    const unsigned long long* Wu = (const unsigned long long*)W;
    const unsigned long long* Iu = (const unsigned long long*)in;

    unsigned long long wl[32], wh[32];
#pragma unroll
    for (int k = 0; k < 32; k++) {
        wl[k] = Wu[l * 32 + k];
        wh[k] = Wu[(l + 32) * 32 + k];
    }
    const float biasl = ba[l] + bb[l];
    const float biash = ba[l + 32] + bb[l + 32];

    const int warpId = blockIdx.x * 4 + wrp;
    const int nw     = gridDim.x * 4;
    const long stride = 2L * nw;

    long r = 2L * warpId;
    if (r >= nrows) return;
    unsigned long long xv0 = Iu[r * 32 + l];
    unsigned long long xv1 = (r + 1 < nrows) ? Iu[(r + 1) * 32 + l] : 0ull;
    int buf = 0;

    while (r < nrows) {
        xsm[wrp][buf][0][l] = xv0;
        xsm[wrp][buf][1][l] = xv1;
        __syncwarp();

        long rn = r + stride;
        if (rn < nrows) {
            xv0 = Iu[rn * 32 + l];
            xv1 = (rn + 1 < nrows) ? Iu[(rn + 1) * 32 + l] : 0ull;
        }

        unsigned long long a0 = pack2(biasl, 0.f), a1 = 0ull;
        unsigned long long c0 = pack2(biash, 0.f), c1 = 0ull;
        unsigned long long d0 = pack2(biasl, 0.f), d1 = 0ull;
        unsigned long long e0 = pack2(biash, 0.f), e1 = 0ull;
        const ulonglong2* xp0 = (const ulonglong2*)&xsm[wrp][buf][0][0];
        const ulonglong2* xp1 = (const ulonglong2*)&xsm[wrp][buf][1][0];
#pragma unroll
        for (int k = 0; k < 32; k += 2) {
            ulonglong2 v0 = xp0[k >> 1];   // row r   (broadcast LDS.128)
            ulonglong2 v1 = xp1[k >> 1];   // row r+1 (broadcast LDS.128)
            a0 = fma2(wl[k],     v0.x, a0);
            a1 = fma2(wl[k + 1], v0.y, a1);
            c0 = fma2(wh[k],     v0.x, c0);
            c1 = fma2(wh[k + 1], v0.y, c1);
            d0 = fma2(wl[k],     v1.x, d0);
            d1 = fma2(wl[k + 1], v1.y, d1);
            e0 = fma2(wh[k],     v1.x, e0);
            e1 = fma2(wh[k + 1], v1.y, e1);
        }
        float s0, s1, t0, t1, u0, u1, q0, q1;
        unpack2(add2(a0, a1), s0, s1);
        unpack2(add2(c0, c1), t0, t1);
        unpack2(add2(d0, d1), u0, u1);
        unpack2(add2(e0, e1), q0, q1);
        out[r * 64 + l]      = s0 + s1;
        out[r * 64 + 32 + l] = t0 + t1;
        if (r + 1 < nrows) {
            out[(r + 1) * 64 + l]      = u0 + u1;
            out[(r + 1) * 64 + 32 + l] = q0 + q1;
        }

        buf ^= 1;
        r = rn;
    }
}

// ============================================================================
// scan: h_t = tanh(xin_t + W_hh h_{t-1}).
// Block = 256 threads = 4 batches x 2 warps. Warp pair (bl) syncs via its own
// NAMED barrier (id bl+1, 64 threads) -> independent batches never couple,
// and each SMSP hosts 2 warps from different batches (latency overlap).
// ============================================================================
__global__ void __launch_bounds__(256) scan_kernel(
    const float* __restrict__ xin, const float* __restrict__ Whh,
    float* __restrict__ hout)
{
    __shared__ __align__(16) float hsm[4][2][64];
    const int l    = threadIdx.x & 31;
    const int wid  = threadIdx.x >> 5;
    const int bl   = wid >> 1;        // batch slot in block (0..3)
    const int half = wid & 1;         // output half
    const int j    = half * 32 + l;   // owned output index
    const int b    = blockIdx.x * 4 + bl;
    const int barid = bl + 1;

    const unsigned long long* Wu = (const unsigned long long*)Whh;
    unsigned long long w[32];
#pragma unroll
    for (int k = 0; k < 32; k++) w[k] = Wu[j * 32 + k];

    hsm[bl][0][j] = 0.f;

    const float* xb = xin  + (long)b * T_ * 64;
    float*       hb = hout + (long)b * T_ * 64;

    float xs[PF];
#pragma unroll
    for (int s = 0; s < PF; s++) xs[s] = xb[s * 64 + j];

    NAMED_BAR(barid, 64);

    int p = 0;
    for (int tb = 0; tb < T_; tb += PF) {
#pragma unroll
        for (int u = 0; u < PF; u++) {
            const int t = tb + u;
            const float xv = xs[u];
            if (t + PF < T_) xs[u] = xb[(t + PF) * 64 + j];  // deep prefetch

            unsigned long long a0 = pack2(xv, 0.f), a1 = 0ull, a2 = 0ull, a3 = 0ull;
            const ulonglong2* hp = (const ulonglong2*)&hsm[bl][p][0];
#pragma unroll
            for (int k = 0; k < 32; k += 4) {
                ulonglong2 v0 = hp[(k >> 1)];        // broadcast LDS.128
                ulonglong2 v1 = hp[(k >> 1) + 1];
                a0 = fma2(w[k],     v0.x, a0);
                a1 = fma2(w[k + 1], v0.y, a1);
                a2 = fma2(w[k + 2], v1.x, a2);
                a3 = fma2(w[k + 3], v1.y, a3);
            }
            float s0, s1;
            unpack2(add2(add2(a0, a1), add2(a2, a3)), s0, s1);
            const float hv = fast_tanh(s0 + s1);

            hb[t * 64 + j]    = hv;
            hsm[bl][p ^ 1][j] = hv;
            NAMED_BAR(barid, 64);
            p ^= 1;
        }
    }
}

// ============================================================================
// head: z = relu(h W1^T + b1); out = z W2^T + b2  (O=2). 2 rows/iter.
// ============================================================================
__global__ void __launch_bounds__(128) head_kernel(
    const float* __restrict__ hin, const float* __restrict__ W1,
    const float* __restrict__ b1, const float* __restrict__ W2,
    const float* __restrict__ b2, float* __restrict__ out, int nrows)
{
    __shared__ __align__(16) unsigned long long xsm[4][2][2][32];
    const int l   = threadIdx.x & 31;
    const int wrp = threadIdx.x >> 5;
    const unsigned long long* Wu = (const unsigned long long*)W1;
    const unsigned long long* Iu = (const unsigned long long*)hin;

    unsigned long long wl[32], wh[32];
#pragma unroll
    for (int k = 0; k < 32; k++) {
        wl[k] = Wu[l * 32 + k];
        wh[k] = Wu[(l + 32) * 32 + k];
    }
    const float biasl = b1[l], biash = b1[l + 32];
    const float w20l = W2[l],      w20h = W2[32 + l];
    const float w21l = W2[64 + l], w21h = W2[96 + l];
    const float b20 = b2[0], b21 = b2[1];

    const int warpId = blockIdx.x * 4 + wrp;
    const int nw     = gridDim.x * 4;
    const long stride = 2L * nw;

    long r = 2L * warpId;
    if (r >= nrows) return;
    unsigned long long xv0 = Iu[r * 32 + l];
    unsigned long long xv1 = (r + 1 < nrows) ? Iu[(r + 1) * 32 + l] : 0ull;
    int buf = 0;

    while (r < nrows) {
        xsm[wrp][buf][0][l] = xv0;
        xsm[wrp][buf][1][l] = xv1;
        __syncwarp();

        long rn = r + stride;
        if (rn < nrows) {
            xv0 = Iu[rn * 32 + l];
            xv1 = (rn + 1 < nrows) ? Iu[(rn + 1) * 32 + l] : 0ull;
        }

        unsigned long long a0 = pack2(biasl, 0.f), a1 = 0ull;
        unsigned long long c0 = pack2(biash, 0.f), c1 = 0ull;
        unsigned long long d0 = pack2(biasl, 0.f), d1 = 0ull;
        unsigned long long e0 = pack2(biash, 0.f), e1 = 0ull;
        const ulonglong2* xp0 = (const ulonglong2*)&xsm[wrp][buf][0][0];
        const ulonglong2* xp1 = (const ulonglong2*)&xsm[wrp][buf][1][0];
#pragma unroll
        for (int k = 0; k < 32; k += 2) {
            ulonglong2 v0 = xp0[k >> 1];
            ulonglong2 v1 = xp1[k >> 1];
            a0 = fma2(wl[k],     v0.x, a0);
            a1 = fma2(wl[k + 1], v0.y, a1);
            c0 = fma2(wh[k],     v0.x, c0);
            c1 = fma2(wh[k + 1], v0.y, c1);
            d0 = fma2(wl[k],     v1.x, d0);
            d1 = fma2(wl[k + 1], v1.y, d1);
            e0 = fma2(wh[k],     v1.x, e0);
            e1 = fma2(wh[k + 1], v1.y, e1);
        }
        float s0, s1, t0, t1, u0, u1, q0, q1;
        unpack2(add2(a0, a1), s0, s1);
        unpack2(add2(c0, c1), t0, t1);
        unpack2(add2(d0, d1), u0, u1);
        unpack2(add2(e0, e1), q0, q1);

        float z0 = fmaxf(s0 + s1, 0.f);
        float z1 = fmaxf(t0 + t1, 0.f);
        float y0 = fmaxf(u0 + u1, 0.f);
        float y1 = fmaxf(q0 + q1, 0.f);

        float p0 = z0 * w20l + z1 * w20h;
        float p1 = z0 * w21l + z1 * w21h;
        float p2 = y0 * w20l + y1 * w20h;
        float p3 = y0 * w21l + y1 * w21h;
#pragma unroll
        for (int off = 16; off; off >>= 1) {
            p0 += __shfl_xor_sync(0xffffffffu, p0, off);
            p1 += __shfl_xor_sync(0xffffffffu, p1, off);
            p2 += __shfl_xor_sync(0xffffffffu, p2, off);
            p3 += __shfl_xor_sync(0xffffffffu, p3, off);
        }
        if (l == 0) {
            *reinterpret_cast<float2*>(&out[r * 2]) = make_float2(p0 + b20, p1 + b21);
            if (r + 1 < nrows)
                *reinterpret_cast<float2*>(&out[(r + 1) * 2]) = make_float2(p2 + b20, p3 + b21);
        }

        buf ^= 1;
        r = rn;
    }
}

// ============================================================================
extern "C" void kernel_launch(void* const* d_in, const int* in_sizes, int n_in,
                              void* d_out, int out_size)
{
    const float* x     = (const float*)d_in[0];
    const float* W_ih0 = (const float*)d_in[1];
    const float* W_hh0 = (const float*)d_in[2];
    const float* b_ih0 = (const float*)d_in[3];
    const float* b_hh0 = (const float*)d_in[4];
    const float* W_ih1 = (const float*)d_in[5];
    const float* W_hh1 = (const float*)d_in[6];
    const float* b_ih1 = (const float*)d_in[7];
    const float* b_hh1 = (const float*)d_in[8];
    const float* W1    = (const float*)d_in[9];
    const float* b1    = (const float*)d_in[10];
    const float* W2    = (const float*)d_in[11];
    const float* b2    = (const float*)d_in[12];
    float* out = (float*)d_out;

    static float* bufA = nullptr;
    static float* bufB = nullptr;
    if (!bufA) {
        cudaGetSymbolAddress((void**)&bufA, g_bufA);
        cudaGetSymbolAddress((void**)&bufB, g_bufB);
    }

    const int GRID = 592;   // 2368 warps x 2 rows/iter; ~12 warps resident/SM

    gemm64_kernel<<<GRID, 128>>>(x, W_ih0, b_ih0, b_hh0, bufA, NROWS);
    scan_kernel<<<B_ / 4, 256>>>(bufA, W_hh0, bufB);
    gemm64_kernel<<<GRID, 128>>>(bufB, W_ih1, b_ih1, b_hh1, bufA, NROWS);
    scan_kernel<<<B_ / 4, 256>>>(bufA, W_hh1, bufB);
    head_kernel<<<GRID, 128>>>(bufB, W1, b1, W2, b2, out, NROWS);
}

// round 4
// speedup vs baseline: 2.6491x; 1.4827x over previous
#include <cuda_runtime.h>

#define B_  256
#define T_  2048
#define H_  64
#define O_  2
#define NROWS (B_ * T_)
#define PF  4   // fused-scan xin prefetch depth (T_ % PF == 0)

// Scratch (device globals — no allocation allowed in kernel_launch)
__device__ float g_bufA[NROWS * H_];
__device__ float g_bufB[NROWS * H_];

// ---------- packed f32x2 helpers (sm_103a FFMA2 path) ----------
static __device__ __forceinline__ unsigned long long pack2(float lo, float hi) {
    unsigned long long r;
    asm("mov.b64 %0, {%1, %2};" : "=l"(r) : "f"(lo), "f"(hi));
    return r;
}
static __device__ __forceinline__ void unpack2(unsigned long long v, float& a, float& b) {
    asm("mov.b64 {%0, %1}, %2;" : "=f"(a), "=f"(b) : "l"(v));
}
static __device__ __forceinline__ unsigned long long fma2(unsigned long long a,
                                                          unsigned long long b,
                                                          unsigned long long c) {
    unsigned long long d;
    asm("fma.rn.f32x2 %0, %1, %2, %3;" : "=l"(d) : "l"(a), "l"(b), "l"(c));
    return d;
}
static __device__ __forceinline__ unsigned long long add2(unsigned long long a,
                                                          unsigned long long b) {
    unsigned long long d;
    asm("add.rn.f32x2 %0, %1, %2;" : "=l"(d) : "l"(a), "l"(b));
    return d;
}

// Fast tanh, rel err ~1e-7, saturates correctly.
static __device__ __forceinline__ float fast_tanh(float x) {
    float e = __expf(2.0f * x);
    return 1.0f - __fdividef(2.0f, e + 1.0f);
}

#define NAMED_BAR(id, cnt) asm volatile("bar.sync %0, %1;" :: "r"(id), "r"(cnt) : "memory")

// ============================================================================
// gemm64: out[r][j] = sum_k in[r][k] * W[j][k] + ba[j] + bb[j]
// Warp handles 2 rows/iter, K-paired f32x2, broadcast LDS.128 staging.
// ============================================================================
__global__ void __launch_bounds__(128) gemm64_kernel(
    const float* __restrict__ in, const float* __restrict__ W,
    const float* __restrict__ ba, const float* __restrict__ bb,
    float* __restrict__ out, int nrows)
{
    __shared__ __align__(16) unsigned long long xsm[4][2][2][32];
    const int l   = threadIdx.x & 31;
    const int wrp = threadIdx.x >> 5;
    const unsigned long long* Wu = (const unsigned long long*)W;
    const unsigned long long* Iu = (const unsigned long long*)in;

    unsigned long long wl[32], wh[32];
#pragma unroll
    for (int k = 0; k < 32; k++) {
        wl[k] = Wu[l * 32 + k];
        wh[k] = Wu[(l + 32) * 32 + k];
    }
    const float biasl = ba[l] + bb[l];
    const float biash = ba[l + 32] + bb[l + 32];

    const int warpId = blockIdx.x * 4 + wrp;
    const int nw     = gridDim.x * 4;
    const long stride = 2L * nw;

    long r = 2L * warpId;
    if (r >= nrows) return;
    unsigned long long xv0 = Iu[r * 32 + l];
    unsigned long long xv1 = (r + 1 < nrows) ? Iu[(r + 1) * 32 + l] : 0ull;
    int buf = 0;

    while (r < nrows) {
        xsm[wrp][buf][0][l] = xv0;
        xsm[wrp][buf][1][l] = xv1;
        __syncwarp();

        long rn = r + stride;
        if (rn < nrows) {
            xv0 = Iu[rn * 32 + l];
            xv1 = (rn + 1 < nrows) ? Iu[(rn + 1) * 32 + l] : 0ull;
        }

        unsigned long long a0 = pack2(biasl, 0.f), a1 = 0ull;
        unsigned long long c0 = pack2(biash, 0.f), c1 = 0ull;
        unsigned long long d0 = pack2(biasl, 0.f), d1 = 0ull;
        unsigned long long e0 = pack2(biash, 0.f), e1 = 0ull;
        const ulonglong2* xp0 = (const ulonglong2*)&xsm[wrp][buf][0][0];
        const ulonglong2* xp1 = (const ulonglong2*)&xsm[wrp][buf][1][0];
#pragma unroll
        for (int k = 0; k < 32; k += 2) {
            ulonglong2 v0 = xp0[k >> 1];
            ulonglong2 v1 = xp1[k >> 1];
            a0 = fma2(wl[k],     v0.x, a0);
            a1 = fma2(wl[k + 1], v0.y, a1);
            c0 = fma2(wh[k],     v0.x, c0);
            c1 = fma2(wh[k + 1], v0.y, c1);
            d0 = fma2(wl[k],     v1.x, d0);
            d1 = fma2(wl[k + 1], v1.y, d1);
            e0 = fma2(wh[k],     v1.x, e0);
            e1 = fma2(wh[k + 1], v1.y, e1);
        }
        float s0, s1, t0, t1, u0, u1, q0, q1;
        unpack2(add2(a0, a1), s0, s1);
        unpack2(add2(c0, c1), t0, t1);
        unpack2(add2(d0, d1), u0, u1);
        unpack2(add2(e0, e1), q0, q1);
        out[r * 64 + l]      = s0 + s1;
        out[r * 64 + 32 + l] = t0 + t1;
        if (r + 1 < nrows) {
            out[(r + 1) * 64 + l]      = u0 + u1;
            out[(r + 1) * 64 + 32 + l] = q0 + q1;
        }

        buf ^= 1;
        r = rn;
    }
}

// ============================================================================
// fused_scan: both RNN layers in one pass.
//   h0_t = tanh(xin0_t + W_hh0 h0_{t-1})
//   h1_t = tanh(W_ih1 h0_t + b1 + W_hh1 h1_{t-1})
// Block = 128 threads = 2 batches x 2 warps (each warp on its own SMSP).
// Lane owns ONE output j = half*32+l per matvec -> 3 weight matrices fit in
// registers (3 x 64). ONE named barrier per step: it publishes h0_t AND the
// previous step's h1 (bar.sync orders all prior smem writes).
// ============================================================================
__global__ void __launch_bounds__(128) fused_scan_kernel(
    const float* __restrict__ xin0,
    const float* __restrict__ Whh0, const float* __restrict__ Wih1,
    const float* __restrict__ Whh1,
    const float* __restrict__ b_ih1, const float* __restrict__ b_hh1,
    float* __restrict__ h1out)
{
    __shared__ __align__(16) float h0sm[2][2][64];
    __shared__ __align__(16) float h1sm[2][2][64];
    const int l    = threadIdx.x & 31;
    const int wid  = threadIdx.x >> 5;
    const int bl   = wid >> 1;        // batch slot (0..1)
    const int half = wid & 1;
    const int j    = half * 32 + l;   // owned output
    const int b    = blockIdx.x * 2 + bl;
    const int barid = bl + 1;

    const unsigned long long* W0u = (const unsigned long long*)Whh0;
    const unsigned long long* Wxu = (const unsigned long long*)Wih1;
    const unsigned long long* W1u = (const unsigned long long*)Whh1;
    unsigned long long w0[32], wx[32], w1[32];
#pragma unroll
    for (int k = 0; k < 32; k++) {
        w0[k] = W0u[j * 32 + k];
        wx[k] = Wxu[j * 32 + k];
        w1[k] = W1u[j * 32 + k];
    }
    const float bias1 = b_ih1[j] + b_hh1[j];

    h0sm[bl][0][j] = 0.f;
    h1sm[bl][0][j] = 0.f;

    const float* xb = xin0  + (long)b * T_ * 64;
    float*       hb = h1out + (long)b * T_ * 64;

    float xs[PF];
#pragma unroll
    for (int s = 0; s < PF; s++) xs[s] = xb[s * 64 + j];

    NAMED_BAR(barid, 64);

    int p = 0;
    for (int tb = 0; tb < T_; tb += PF) {
#pragma unroll
        for (int u = 0; u < PF; u++) {
            const int t = tb + u;
            const float xv = xs[u];
            if (t + PF < T_) xs[u] = xb[(t + PF) * 64 + j];

            // ---- layer 0 recurrence: acc0 = xv + Whh0 . h0_old ----
            unsigned long long a0 = pack2(xv, 0.f), a1 = 0ull, a2 = 0ull, a3 = 0ull;
            {
                const ulonglong2* hp = (const ulonglong2*)&h0sm[bl][p][0];
#pragma unroll
                for (int k = 0; k < 32; k += 4) {
                    ulonglong2 v0 = hp[(k >> 1)];
                    ulonglong2 v1 = hp[(k >> 1) + 1];
                    a0 = fma2(w0[k],     v0.x, a0);
                    a1 = fma2(w0[k + 1], v0.y, a1);
                    a2 = fma2(w0[k + 2], v1.x, a2);
                    a3 = fma2(w0[k + 3], v1.y, a3);
                }
            }
            float s0, s1;
            unpack2(add2(add2(a0, a1), add2(a2, a3)), s0, s1);
            const float h0v = fast_tanh(s0 + s1);
            h0sm[bl][p ^ 1][j] = h0v;

            NAMED_BAR(barid, 64);   // publishes h0_t AND last step's h1

            // ---- layer 1: accx = Wih1 . h0_new ; acc1 = Whh1 . h1_old ----
            unsigned long long c0 = pack2(bias1, 0.f), c1 = 0ull, c2 = 0ull, c3 = 0ull;
            unsigned long long d0 = 0ull, d1 = 0ull, d2 = 0ull, d3 = 0ull;
            {
                const ulonglong2* hpx = (const ulonglong2*)&h0sm[bl][p ^ 1][0];
                const ulonglong2* hp1 = (const ulonglong2*)&h1sm[bl][p][0];
#pragma unroll
                for (int k = 0; k < 32; k += 4) {
                    ulonglong2 vx0 = hpx[(k >> 1)];
                    ulonglong2 vx1 = hpx[(k >> 1) + 1];
                    ulonglong2 vh0 = hp1[(k >> 1)];
                    ulonglong2 vh1 = hp1[(k >> 1) + 1];
                    c0 = fma2(wx[k],     vx0.x, c0);
                    c1 = fma2(wx[k + 1], vx0.y, c1);
                    d0 = fma2(w1[k],     vh0.x, d0);
                    d1 = fma2(w1[k + 1], vh0.y, d1);
                    c2 = fma2(wx[k + 2], vx1.x, c2);
                    c3 = fma2(wx[k + 3], vx1.y, c3);
                    d2 = fma2(w1[k + 2], vh1.x, d2);
                    d3 = fma2(w1[k + 3], vh1.y, d3);
                }
            }
            float e0, e1;
            unpack2(add2(add2(add2(c0, c1), add2(c2, c3)),
                         add2(add2(d0, d1), add2(d2, d3))), e0, e1);
            const float h1v = fast_tanh(e0 + e1);

            hb[t * 64 + j]    = h1v;
            h1sm[bl][p ^ 1][j] = h1v;   // made visible by NEXT step's barrier
            p ^= 1;
        }
    }
}

// ============================================================================
// head: z = relu(h W1^T + b1); out = z W2^T + b2  (O=2). 2 rows/iter.
// ============================================================================
__global__ void __launch_bounds__(128) head_kernel(
    const float* __restrict__ hin, const float* __restrict__ W1,
    const float* __restrict__ b1, const float* __restrict__ W2,
    const float* __restrict__ b2, float* __restrict__ out, int nrows)
{
    __shared__ __align__(16) unsigned long long xsm[4][2][2][32];
    const int l   = threadIdx.x & 31;
    const int wrp = threadIdx.x >> 5;
    const unsigned long long* Wu = (const unsigned long long*)W1;
    const unsigned long long* Iu = (const unsigned long long*)hin;

    unsigned long long wl[32], wh[32];
#pragma unroll
    for (int k = 0; k < 32; k++) {
        wl[k] = Wu[l * 32 + k];
        wh[k] = Wu[(l + 32) * 32 + k];
    }
    const float biasl = b1[l], biash = b1[l + 32];
    const float w20l = W2[l],      w20h = W2[32 + l];
    const float w21l = W2[64 + l], w21h = W2[96 + l];
    const float b20 = b2[0], b21 = b2[1];

    const int warpId = blockIdx.x * 4 + wrp;
    const int nw     = gridDim.x * 4;
    const long stride = 2L * nw;

    long r = 2L * warpId;
    if (r >= nrows) return;
    unsigned long long xv0 = Iu[r * 32 + l];
    unsigned long long xv1 = (r + 1 < nrows) ? Iu[(r + 1) * 32 + l] : 0ull;
    int buf = 0;

    while (r < nrows) {
        xsm[wrp][buf][0][l] = xv0;
        xsm[wrp][buf][1][l] = xv1;
        __syncwarp();

        long rn = r + stride;
        if (rn < nrows) {
            xv0 = Iu[rn * 32 + l];
            xv1 = (rn + 1 < nrows) ? Iu[(rn + 1) * 32 + l] : 0ull;
        }

        unsigned long long a0 = pack2(biasl, 0.f), a1 = 0ull;
        unsigned long long c0 = pack2(biash, 0.f), c1 = 0ull;
        unsigned long long d0 = pack2(biasl, 0.f), d1 = 0ull;
        unsigned long long e0 = pack2(biash, 0.f), e1 = 0ull;
        const ulonglong2* xp0 = (const ulonglong2*)&xsm[wrp][buf][0][0];
        const ulonglong2* xp1 = (const ulonglong2*)&xsm[wrp][buf][1][0];
#pragma unroll
        for (int k = 0; k < 32; k += 2) {
            ulonglong2 v0 = xp0[k >> 1];
            ulonglong2 v1 = xp1[k >> 1];
            a0 = fma2(wl[k],     v0.x, a0);
            a1 = fma2(wl[k + 1], v0.y, a1);
            c0 = fma2(wh[k],     v0.x, c0);
            c1 = fma2(wh[k + 1], v0.y, c1);
            d0 = fma2(wl[k],     v1.x, d0);
            d1 = fma2(wl[k + 1], v1.y, d1);
            e0 = fma2(wh[k],     v1.x, e0);
            e1 = fma2(wh[k + 1], v1.y, e1);
        }
        float s0, s1, t0, t1, u0, u1, q0, q1;
        unpack2(add2(a0, a1), s0, s1);
        unpack2(add2(c0, c1), t0, t1);
        unpack2(add2(d0, d1), u0, u1);
        unpack2(add2(e0, e1), q0, q1);

        float z0 = fmaxf(s0 + s1, 0.f);
        float z1 = fmaxf(t0 + t1, 0.f);
        float y0 = fmaxf(u0 + u1, 0.f);
        float y1 = fmaxf(q0 + q1, 0.f);

        float p0 = z0 * w20l + z1 * w20h;
        float p1 = z0 * w21l + z1 * w21h;
        float p2 = y0 * w20l + y1 * w20h;
        float p3 = y0 * w21l + y1 * w21h;
#pragma unroll
        for (int off = 16; off; off >>= 1) {
            p0 += __shfl_xor_sync(0xffffffffu, p0, off);
            p1 += __shfl_xor_sync(0xffffffffu, p1, off);
            p2 += __shfl_xor_sync(0xffffffffu, p2, off);
            p3 += __shfl_xor_sync(0xffffffffu, p3, off);
        }
        if (l == 0) {
            *reinterpret_cast<float2*>(&out[r * 2]) = make_float2(p0 + b20, p1 + b21);
            if (r + 1 < nrows)
                *reinterpret_cast<float2*>(&out[(r + 1) * 2]) = make_float2(p2 + b20, p3 + b21);
        }

        buf ^= 1;
        r = rn;
    }
}

// ============================================================================
extern "C" void kernel_launch(void* const* d_in, const int* in_sizes, int n_in,
                              void* d_out, int out_size)
{
    const float* x     = (const float*)d_in[0];
    const float* W_ih0 = (const float*)d_in[1];
    const float* W_hh0 = (const float*)d_in[2];
    const float* b_ih0 = (const float*)d_in[3];
    const float* b_hh0 = (const float*)d_in[4];
    const float* W_ih1 = (const float*)d_in[5];
    const float* W_hh1 = (const float*)d_in[6];
    const float* b_ih1 = (const float*)d_in[7];
    const float* b_hh1 = (const float*)d_in[8];
    const float* W1    = (const float*)d_in[9];
    const float* b1    = (const float*)d_in[10];
    const float* W2    = (const float*)d_in[11];
    const float* b2    = (const float*)d_in[12];
    float* out = (float*)d_out;

    static float* bufA = nullptr;
    static float* bufB = nullptr;
    if (!bufA) {
        cudaGetSymbolAddress((void**)&bufA, g_bufA);
        cudaGetSymbolAddress((void**)&bufB, g_bufB);
    }

    const int GRID = 1184;  // 8 warps/SMSP: saturate fma issue on parallel kernels

    // xin0 = x W_ih0^T + b_ih0 + b_hh0
    gemm64_kernel<<<GRID, 128>>>(x, W_ih0, b_ih0, b_hh0, bufA, NROWS);
    // both RNN layers fused -> h1
    fused_scan_kernel<<<B_ / 2, 128>>>(bufA, W_hh0, W_ih1, W_hh1,
                                       b_ih1, b_hh1, bufB);
    // head
    head_kernel<<<GRID, 128>>>(bufB, W1, b1, W2, b2, out, NROWS);
}